// round 2
// baseline (speedup 1.0000x reference)
#include <cuda_runtime.h>
#include <mma.h>
#include <math.h>

using namespace nvcuda;

#define S_LEN 2048
#define DM    1024
#define NH    16
#define HD    64

// Scratch (allocation-guard rules: __device__ globals).
__device__ float g_q[S_LEN * DM];
__device__ float g_k[S_LEN * DM];
__device__ float g_v[S_LEN * DM];
__device__ float g_p0[S_LEN * DM];   // pv split-K partial 0
__device__ float g_p1[S_LEN * DM];   // pv split-K partial 1

// ---------------------------------------------------------------------------
// Kernel 1: QKV projection.  Y = X @ W  (M=2048, N=1024, K=1024), z selects W.
// BM=128, BN=128, BK=16. 256 threads = 8 warps (4 x 2), warp tile 32x64.
// Reg-staged double-buffered smem, one __syncthreads per K-iter.
// ---------------------------------------------------------------------------
__global__ __launch_bounds__(256) void qkv_gemm_kernel(
    const float* __restrict__ X,
    const float* __restrict__ Wq,
    const float* __restrict__ Wk,
    const float* __restrict__ Wv)
{
    constexpr int BM = 128, BN = 128, BK = 16;
    const float* W = (blockIdx.z == 0) ? Wq : (blockIdx.z == 1) ? Wk : Wv;
    float*       Y = (blockIdx.z == 0) ? g_q : (blockIdx.z == 1) ? g_k : g_v;

    __shared__ float As[2][BM][BK + 4];   // 2 x 128 x 20
    __shared__ float Bs[2][BK][BN + 4];   // 2 x 16 x 132

    const int tid  = threadIdx.x;
    const int warp = tid >> 5;
    const int wm   = warp & 3;   // 4 row strips of 32
    const int wn   = warp >> 2;  // 2 col strips of 64

    const int row0 = blockIdx.y * BM;
    const int col0 = blockIdx.x * BN;

    wmma::fragment<wmma::accumulator, 16, 16, 8, float> acc[2][4];
    #pragma unroll
    for (int i = 0; i < 2; i++)
        #pragma unroll
        for (int j = 0; j < 4; j++)
            wmma::fill_fragment(acc[i][j], 0.0f);

    float4 aR[2], bR[2];

    // gmem -> regs for K-slab starting at k0
    auto gload = [&](int k0) {
        #pragma unroll
        for (int it = 0; it < 2; it++) {
            int idx = tid + it * 256;                 // A: 128 rows x 4 f4
            int r = idx >> 2, c4 = idx & 3;
            aR[it] = *(const float4*)&X[(size_t)(row0 + r) * DM + k0 + c4 * 4];
        }
        #pragma unroll
        for (int it = 0; it < 2; it++) {
            int idx = tid + it * 256;                 // B: 16 rows x 32 f4
            int r = idx >> 5, c4 = idx & 31;
            bR[it] = *(const float4*)&W[(size_t)(k0 + r) * DM + col0 + c4 * 4];
        }
    };
    auto sts = [&](int buf) {
        #pragma unroll
        for (int it = 0; it < 2; it++) {
            int idx = tid + it * 256;
            int r = idx >> 2, c4 = idx & 3;
            *(float4*)&As[buf][r][c4 * 4] = aR[it];
        }
        #pragma unroll
        for (int it = 0; it < 2; it++) {
            int idx = tid + it * 256;
            int r = idx >> 5, c4 = idx & 31;
            *(float4*)&Bs[buf][r][c4 * 4] = bR[it];
        }
    };

    gload(0);
    sts(0);
    __syncthreads();

    const int nIter = DM / BK;   // 64
    for (int i = 0; i < nIter; i++) {
        const int cur = i & 1;
        if (i + 1 < nIter) gload((i + 1) * BK);

        #pragma unroll
        for (int kk = 0; kk < BK; kk += 8) {
            wmma::fragment<wmma::matrix_a, 16, 16, 8, wmma::precision::tf32,
                           wmma::row_major> a[2];
            wmma::fragment<wmma::matrix_b, 16, 16, 8, wmma::precision::tf32,
                           wmma::row_major> b[4];
            #pragma unroll
            for (int ii = 0; ii < 2; ii++) {
                wmma::load_matrix_sync(a[ii], &As[cur][wm * 32 + ii * 16][kk], BK + 4);
                #pragma unroll
                for (int e = 0; e < a[ii].num_elements; e++)
                    a[ii].x[e] = wmma::__float_to_tf32(a[ii].x[e]);
            }
            #pragma unroll
            for (int j = 0; j < 4; j++) {
                wmma::load_matrix_sync(b[j], &Bs[cur][kk][wn * 64 + j * 16], BN + 4);
                #pragma unroll
                for (int e = 0; e < b[j].num_elements; e++)
                    b[j].x[e] = wmma::__float_to_tf32(b[j].x[e]);
            }
            #pragma unroll
            for (int ii = 0; ii < 2; ii++)
                #pragma unroll
                for (int j = 0; j < 4; j++)
                    wmma::mma_sync(acc[ii][j], a[ii], b[j], acc[ii][j]);
        }

        if (i + 1 < nIter) sts(cur ^ 1);
        __syncthreads();
    }

    #pragma unroll
    for (int i = 0; i < 2; i++)
        #pragma unroll
        for (int j = 0; j < 4; j++)
            wmma::store_matrix_sync(
                &Y[(size_t)(row0 + wm * 32 + i * 16) * DM + col0 + wn * 64 + j * 16],
                acc[i][j], DM, wmma::mem_row_major);
}

// ---------------------------------------------------------------------------
// Kernel 2: scores[h][q][k] = (q_h . k_h) / 8  (unchanged from round 1)
// ---------------------------------------------------------------------------
__global__ __launch_bounds__(128) void scores_kernel(float* __restrict__ probs)
{
    const int h = blockIdx.z;
    __shared__ float Qs[64][68];
    __shared__ float Ks[64][68];

    const int tid  = threadIdx.x;
    const int warp = tid >> 5;
    const int wm   = warp & 1;
    const int wn   = warp >> 1;

    const int qrow0 = blockIdx.y * 64;
    const int krow0 = blockIdx.x * 64;
    const float* qp = g_q + h * HD;
    const float* kp = g_k + h * HD;

    for (int idx = tid; idx < 64 * 16; idx += 128) {
        int r = idx >> 4, c4 = idx & 15;
        *(float4*)&Qs[r][c4 * 4] =
            *(const float4*)&qp[(size_t)(qrow0 + r) * DM + c4 * 4];
        *(float4*)&Ks[r][c4 * 4] =
            *(const float4*)&kp[(size_t)(krow0 + r) * DM + c4 * 4];
    }
    __syncthreads();

    wmma::fragment<wmma::accumulator, 16, 16, 8, float> acc[2][2];
    #pragma unroll
    for (int i = 0; i < 2; i++)
        #pragma unroll
        for (int j = 0; j < 2; j++)
            wmma::fill_fragment(acc[i][j], 0.0f);

    #pragma unroll
    for (int kk = 0; kk < 64; kk += 8) {
        wmma::fragment<wmma::matrix_a, 16, 16, 8, wmma::precision::tf32,
                       wmma::row_major> a[2];
        wmma::fragment<wmma::matrix_b, 16, 16, 8, wmma::precision::tf32,
                       wmma::col_major> b[2];
        #pragma unroll
        for (int i = 0; i < 2; i++) {
            wmma::load_matrix_sync(a[i], &Qs[wm * 32 + i * 16][kk], 68);
            #pragma unroll
            for (int e = 0; e < a[i].num_elements; e++)
                a[i].x[e] = wmma::__float_to_tf32(a[i].x[e]);
        }
        #pragma unroll
        for (int j = 0; j < 2; j++) {
            wmma::load_matrix_sync(b[j], &Ks[wn * 32 + j * 16][kk], 68);
            #pragma unroll
            for (int e = 0; e < b[j].num_elements; e++)
                b[j].x[e] = wmma::__float_to_tf32(b[j].x[e]);
        }
        #pragma unroll
        for (int i = 0; i < 2; i++)
            #pragma unroll
            for (int j = 0; j < 2; j++)
                wmma::mma_sync(acc[i][j], a[i], b[j], acc[i][j]);
    }

    float* outp = probs + (size_t)h * S_LEN * S_LEN;
    #pragma unroll
    for (int i = 0; i < 2; i++)
        #pragma unroll
        for (int j = 0; j < 2; j++) {
            #pragma unroll
            for (int e = 0; e < acc[i][j].num_elements; e++)
                acc[i][j].x[e] *= 0.125f;
            wmma::store_matrix_sync(
                &outp[(size_t)(qrow0 + wm * 32 + i * 16) * S_LEN +
                      krow0 + wn * 32 + j * 16],
                acc[i][j], S_LEN, wmma::mem_row_major);
        }
}

// ---------------------------------------------------------------------------
// Kernel 3: row softmax in place, float4 + __expf. One block per row.
// ---------------------------------------------------------------------------
__global__ __launch_bounds__(256) void softmax_kernel(float* __restrict__ probs)
{
    float4* row4 = (float4*)(probs + (size_t)blockIdx.x * S_LEN);
    const int tid  = threadIdx.x;
    const int lane = tid & 31;
    const int warp = tid >> 5;
    __shared__ float redm[8];
    __shared__ float reds[8];

    float4 v0 = row4[tid];
    float4 v1 = row4[tid + 256];

    float m = fmaxf(fmaxf(fmaxf(v0.x, v0.y), fmaxf(v0.z, v0.w)),
                    fmaxf(fmaxf(v1.x, v1.y), fmaxf(v1.z, v1.w)));
    #pragma unroll
    for (int o = 16; o > 0; o >>= 1)
        m = fmaxf(m, __shfl_xor_sync(0xFFFFFFFFu, m, o));
    if (lane == 0) redm[warp] = m;
    __syncthreads();
    m = redm[0];
    #pragma unroll
    for (int w = 1; w < 8; w++) m = fmaxf(m, redm[w]);

    v0.x = __expf(v0.x - m); v0.y = __expf(v0.y - m);
    v0.z = __expf(v0.z - m); v0.w = __expf(v0.w - m);
    v1.x = __expf(v1.x - m); v1.y = __expf(v1.y - m);
    v1.z = __expf(v1.z - m); v1.w = __expf(v1.w - m);

    float s = (v0.x + v0.y) + (v0.z + v0.w) + (v1.x + v1.y) + (v1.z + v1.w);
    #pragma unroll
    for (int o = 16; o > 0; o >>= 1)
        s += __shfl_xor_sync(0xFFFFFFFFu, s, o);
    if (lane == 0) reds[warp] = s;
    __syncthreads();
    s = 0.0f;
    #pragma unroll
    for (int w = 0; w < 8; w++) s += reds[w];

    const float inv = 1.0f / s;
    v0.x *= inv; v0.y *= inv; v0.z *= inv; v0.w *= inv;
    v1.x *= inv; v1.y *= inv; v1.z *= inv; v1.w *= inv;
    row4[tid]       = v0;
    row4[tid + 256] = v1;
}

// ---------------------------------------------------------------------------
// Kernel 4: PV with split-K=2. ctx_part[q][h*64+d] = sum_{k in half} p*v.
// BM=64, BK=64. 256 threads = 8 warps (4 x 2), warp tile 16x32.
// grid = (2 ksplit, 32 qstrips, 16 heads) = 1024 blocks.
// ---------------------------------------------------------------------------
__global__ __launch_bounds__(256) void pv_kernel(const float* __restrict__ probs)
{
    constexpr int BM = 64, BK = 64;
    const int h  = blockIdx.z;
    const int kz = blockIdx.x;
    const float* P  = probs + (size_t)h * S_LEN * S_LEN;
    const float* vp = g_v + h * HD;
    float* out = (kz == 0 ? g_p0 : g_p1);

    __shared__ float Ps[BM][BK + 4];
    __shared__ float Vs[BK][HD + 4];

    const int tid  = threadIdx.x;
    const int warp = tid >> 5;
    const int wm   = warp & 3;   // 4 strips of 16 rows
    const int wn   = warp >> 2;  // 2 strips of 32 cols
    const int row0 = blockIdx.y * BM;
    const int kbase = kz * (S_LEN / 2);

    wmma::fragment<wmma::accumulator, 16, 16, 8, float> acc[2];
    wmma::fill_fragment(acc[0], 0.0f);
    wmma::fill_fragment(acc[1], 0.0f);

    float4 pR[4], vR[4];
    auto gload = [&](int k0) {
        #pragma unroll
        for (int it = 0; it < 4; it++) {
            int idx = tid + it * 256;                 // P: 64 rows x 16 f4
            int r = idx >> 4, c4 = idx & 15;
            pR[it] = *(const float4*)&P[(size_t)(row0 + r) * S_LEN + k0 + c4 * 4];
        }
        #pragma unroll
        for (int it = 0; it < 4; it++) {
            int idx = tid + it * 256;                 // V: 64 krows x 16 f4
            int r = idx >> 4, c4 = idx & 15;
            vR[it] = *(const float4*)&vp[(size_t)(k0 + r) * DM + c4 * 4];
        }
    };
    auto sts = [&]() {
        #pragma unroll
        for (int it = 0; it < 4; it++) {
            int idx = tid + it * 256;
            int r = idx >> 4, c4 = idx & 15;
            *(float4*)&Ps[r][c4 * 4] = pR[it];
        }
        #pragma unroll
        for (int it = 0; it < 4; it++) {
            int idx = tid + it * 256;
            int r = idx >> 4, c4 = idx & 15;
            *(float4*)&Vs[r][c4 * 4] = vR[it];
        }
    };

    const int nIter = (S_LEN / 2) / BK;   // 16
    gload(kbase);
    sts();
    __syncthreads();

    for (int i = 0; i < nIter; i++) {
        if (i + 1 < nIter) gload(kbase + (i + 1) * BK);

        #pragma unroll
        for (int kk = 0; kk < BK; kk += 8) {
            wmma::fragment<wmma::matrix_a, 16, 16, 8, wmma::precision::tf32,
                           wmma::row_major> a;
            wmma::fragment<wmma::matrix_b, 16, 16, 8, wmma::precision::tf32,
                           wmma::row_major> b[2];
            wmma::load_matrix_sync(a, &Ps[wm * 16][kk], BK + 4);
            #pragma unroll
            for (int e = 0; e < a.num_elements; e++)
                a.x[e] = wmma::__float_to_tf32(a.x[e]);
            #pragma unroll
            for (int j = 0; j < 2; j++) {
                wmma::load_matrix_sync(b[j], &Vs[kk][wn * 32 + j * 16], HD + 4);
                #pragma unroll
                for (int e = 0; e < b[j].num_elements; e++)
                    b[j].x[e] = wmma::__float_to_tf32(b[j].x[e]);
            }
            wmma::mma_sync(acc[0], a, b[0], acc[0]);
            wmma::mma_sync(acc[1], a, b[1], acc[1]);
        }
        __syncthreads();
        if (i + 1 < nIter) sts();
        __syncthreads();
    }

    #pragma unroll
    for (int j = 0; j < 2; j++)
        wmma::store_matrix_sync(
            &out[(size_t)(row0 + wm * 16) * DM + h * HD + wn * 32 + j * 16],
            acc[j], DM, wmma::mem_row_major);
}

// ---------------------------------------------------------------------------
// Kernel 5: ctx = p0 + p1 (split-K reduction), float4.
// ---------------------------------------------------------------------------
__global__ __launch_bounds__(256) void pv_add_kernel(float* __restrict__ ctx)
{
    size_t i = (size_t)blockIdx.x * 256 + threadIdx.x;
    float4 a = ((const float4*)g_p0)[i];
    float4 b = ((const float4*)g_p1)[i];
    ((float4*)ctx)[i] = make_float4(a.x + b.x, a.y + b.y, a.z + b.z, a.w + b.w);
}

// ---------------------------------------------------------------------------
// Launch. d_out layout: context (2048*1024 floats) then probs (16*2048*2048).
// ---------------------------------------------------------------------------
extern "C" void kernel_launch(void* const* d_in, const int* in_sizes, int n_in,
                              void* d_out, int out_size)
{
    const float* hs = (const float*)d_in[0];
    const float* Wq = (const float*)d_in[1];
    const float* Wk = (const float*)d_in[2];
    const float* Wv = (const float*)d_in[3];

    float* ctx   = (float*)d_out;
    float* probs = ctx + (size_t)S_LEN * DM;

    qkv_gemm_kernel<<<dim3(DM / 128, S_LEN / 128, 3), 256>>>(hs, Wq, Wk, Wv);
    scores_kernel<<<dim3(S_LEN / 64, S_LEN / 64, NH), 128>>>(probs);
    softmax_kernel<<<dim3(NH * S_LEN), 256>>>(probs);
    pv_kernel<<<dim3(2, S_LEN / 64, NH), 256>>>(probs);
    pv_add_kernel<<<dim3(S_LEN * DM / 4 / 256), 256>>>(ctx);
}

// round 3
// speedup vs baseline: 1.0715x; 1.0715x over previous
#include <cuda_runtime.h>
#include <mma.h>
#include <math.h>

using namespace nvcuda;

#define S_LEN 2048
#define DM    1024
#define NH    16
#define HD    64

// Scratch (allocation-guard rules: __device__ globals).
__device__ float g_q[S_LEN * DM];
__device__ float g_k[S_LEN * DM];
__device__ float g_v[S_LEN * DM];

// ---------------------------------------------------------------------------
// Kernel 1: QKV projection (round-1 version, reverted).
// Y = X @ W (M=2048, N=1024, K=1024), z selects W.
// BM=128, BN=64, BK=32. 256 threads = 8 warps (4x2), warp tile 32x32.
// ---------------------------------------------------------------------------
__global__ __launch_bounds__(256) void qkv_gemm_kernel(
    const float* __restrict__ X,
    const float* __restrict__ Wq,
    const float* __restrict__ Wk,
    const float* __restrict__ Wv)
{
    constexpr int BM = 128, BN = 64, BK = 32;
    const float* W = (blockIdx.z == 0) ? Wq : (blockIdx.z == 1) ? Wk : Wv;
    float*       Y = (blockIdx.z == 0) ? g_q : (blockIdx.z == 1) ? g_k : g_v;

    __shared__ float As[BM][BK + 4];
    __shared__ float Bs[BK][BN + 4];

    const int tid  = threadIdx.x;
    const int warp = tid >> 5;
    const int wm   = warp & 3;
    const int wn   = warp >> 2;

    const int row0 = blockIdx.y * BM;
    const int col0 = blockIdx.x * BN;

    wmma::fragment<wmma::accumulator, 16, 16, 8, float> acc[2][2];
    #pragma unroll
    for (int i = 0; i < 2; i++)
        #pragma unroll
        for (int j = 0; j < 2; j++)
            wmma::fill_fragment(acc[i][j], 0.0f);

    for (int k0 = 0; k0 < DM; k0 += BK) {
        #pragma unroll
        for (int it = 0; it < 4; it++) {
            int idx = tid + it * 256;
            int r = idx >> 3, c4 = idx & 7;
            float4 v4 = *(const float4*)&X[(size_t)(row0 + r) * DM + k0 + c4 * 4];
            *(float4*)&As[r][c4 * 4] = v4;
        }
        #pragma unroll
        for (int it = 0; it < 2; it++) {
            int idx = tid + it * 256;
            int r = idx >> 4, c4 = idx & 15;
            float4 v4 = *(const float4*)&W[(size_t)(k0 + r) * DM + col0 + c4 * 4];
            *(float4*)&Bs[r][c4 * 4] = v4;
        }
        __syncthreads();

        #pragma unroll
        for (int kk = 0; kk < BK; kk += 8) {
            wmma::fragment<wmma::matrix_a, 16, 16, 8, wmma::precision::tf32,
                           wmma::row_major> a[2];
            wmma::fragment<wmma::matrix_b, 16, 16, 8, wmma::precision::tf32,
                           wmma::row_major> b[2];
            #pragma unroll
            for (int i = 0; i < 2; i++) {
                wmma::load_matrix_sync(a[i], &As[wm * 32 + i * 16][kk], BK + 4);
                #pragma unroll
                for (int e = 0; e < a[i].num_elements; e++)
                    a[i].x[e] = wmma::__float_to_tf32(a[i].x[e]);
            }
            #pragma unroll
            for (int j = 0; j < 2; j++) {
                wmma::load_matrix_sync(b[j], &Bs[kk][wn * 32 + j * 16], BN + 4);
                #pragma unroll
                for (int e = 0; e < b[j].num_elements; e++)
                    b[j].x[e] = wmma::__float_to_tf32(b[j].x[e]);
            }
            #pragma unroll
            for (int i = 0; i < 2; i++)
                #pragma unroll
                for (int j = 0; j < 2; j++)
                    wmma::mma_sync(acc[i][j], a[i], b[j], acc[i][j]);
        }
        __syncthreads();
    }

    #pragma unroll
    for (int i = 0; i < 2; i++)
        #pragma unroll
        for (int j = 0; j < 2; j++)
            wmma::store_matrix_sync(
                &Y[(size_t)(row0 + wm * 32 + i * 16) * DM + col0 + wn * 32 + j * 16],
                acc[i][j], DM, wmma::mem_row_major);
}

// ---------------------------------------------------------------------------
// Kernel 2: scores[h][q][k] = (q_h . k_h) / 8, 128x128 tile per block.
// 256 threads = 8 warps (4 x 2), warp tile 32x64 (acc 2x4).
// d=64 chunked as 2 x 32 to fit smem (2 x 128 x 36 floats = 36.9KB).
// ---------------------------------------------------------------------------
__global__ __launch_bounds__(256) void scores_kernel(float* __restrict__ probs)
{
    const int h = blockIdx.z;
    __shared__ float Qs[128][36];
    __shared__ float Ks[128][36];

    const int tid  = threadIdx.x;
    const int warp = tid >> 5;
    const int wm   = warp & 3;   // 4 strips of 32 q-rows
    const int wn   = warp >> 2;  // 2 strips of 64 k-cols

    const int qrow0 = blockIdx.y * 128;
    const int krow0 = blockIdx.x * 128;
    const float* qp = g_q + h * HD;
    const float* kp = g_k + h * HD;

    wmma::fragment<wmma::accumulator, 16, 16, 8, float> acc[2][4];
    #pragma unroll
    for (int i = 0; i < 2; i++)
        #pragma unroll
        for (int j = 0; j < 4; j++)
            wmma::fill_fragment(acc[i][j], 0.0f);

    #pragma unroll
    for (int d0 = 0; d0 < HD; d0 += 32) {
        // load 128 x 32 slices of Q and K: 1024 f4 each, 4 per thread each
        #pragma unroll
        for (int it = 0; it < 4; it++) {
            int idx = tid + it * 256;
            int r = idx >> 3, c4 = idx & 7;
            *(float4*)&Qs[r][c4 * 4] =
                *(const float4*)&qp[(size_t)(qrow0 + r) * DM + d0 + c4 * 4];
            *(float4*)&Ks[r][c4 * 4] =
                *(const float4*)&kp[(size_t)(krow0 + r) * DM + d0 + c4 * 4];
        }
        __syncthreads();

        #pragma unroll
        for (int kk = 0; kk < 32; kk += 8) {
            wmma::fragment<wmma::matrix_a, 16, 16, 8, wmma::precision::tf32,
                           wmma::row_major> a[2];
            wmma::fragment<wmma::matrix_b, 16, 16, 8, wmma::precision::tf32,
                           wmma::col_major> b[4];
            #pragma unroll
            for (int i = 0; i < 2; i++) {
                wmma::load_matrix_sync(a[i], &Qs[wm * 32 + i * 16][kk], 36);
                #pragma unroll
                for (int e = 0; e < a[i].num_elements; e++)
                    a[i].x[e] = wmma::__float_to_tf32(a[i].x[e]);
            }
            #pragma unroll
            for (int j = 0; j < 4; j++) {
                // col_major: element (k,n) at base[n*36 + k]; base = &Ks[n0][kk]
                wmma::load_matrix_sync(b[j], &Ks[wn * 64 + j * 16][kk], 36);
                #pragma unroll
                for (int e = 0; e < b[j].num_elements; e++)
                    b[j].x[e] = wmma::__float_to_tf32(b[j].x[e]);
            }
            #pragma unroll
            for (int i = 0; i < 2; i++)
                #pragma unroll
                for (int j = 0; j < 4; j++)
                    wmma::mma_sync(acc[i][j], a[i], b[j], acc[i][j]);
        }
        __syncthreads();
    }

    float* outp = probs + (size_t)h * S_LEN * S_LEN;
    #pragma unroll
    for (int i = 0; i < 2; i++)
        #pragma unroll
        for (int j = 0; j < 4; j++) {
            #pragma unroll
            for (int e = 0; e < acc[i][j].num_elements; e++)
                acc[i][j].x[e] *= 0.125f;   // 1/sqrt(64)
            wmma::store_matrix_sync(
                &outp[(size_t)(qrow0 + wm * 32 + i * 16) * S_LEN +
                      krow0 + wn * 64 + j * 16],
                acc[i][j], S_LEN, wmma::mem_row_major);
        }
}

// ---------------------------------------------------------------------------
// Kernel 3: row softmax in place, float4 + __expf. One block per row.
// ---------------------------------------------------------------------------
__global__ __launch_bounds__(256) void softmax_kernel(float* __restrict__ probs)
{
    float4* row4 = (float4*)(probs + (size_t)blockIdx.x * S_LEN);
    const int tid  = threadIdx.x;
    const int lane = tid & 31;
    const int warp = tid >> 5;
    __shared__ float redm[8];
    __shared__ float reds[8];

    float4 v0 = row4[tid];
    float4 v1 = row4[tid + 256];

    float m = fmaxf(fmaxf(fmaxf(v0.x, v0.y), fmaxf(v0.z, v0.w)),
                    fmaxf(fmaxf(v1.x, v1.y), fmaxf(v1.z, v1.w)));
    #pragma unroll
    for (int o = 16; o > 0; o >>= 1)
        m = fmaxf(m, __shfl_xor_sync(0xFFFFFFFFu, m, o));
    if (lane == 0) redm[warp] = m;
    __syncthreads();
    m = redm[0];
    #pragma unroll
    for (int w = 1; w < 8; w++) m = fmaxf(m, redm[w]);

    v0.x = __expf(v0.x - m); v0.y = __expf(v0.y - m);
    v0.z = __expf(v0.z - m); v0.w = __expf(v0.w - m);
    v1.x = __expf(v1.x - m); v1.y = __expf(v1.y - m);
    v1.z = __expf(v1.z - m); v1.w = __expf(v1.w - m);

    float s = (v0.x + v0.y) + (v0.z + v0.w) + (v1.x + v1.y) + (v1.z + v1.w);
    #pragma unroll
    for (int o = 16; o > 0; o >>= 1)
        s += __shfl_xor_sync(0xFFFFFFFFu, s, o);
    if (lane == 0) reds[warp] = s;
    __syncthreads();
    s = 0.0f;
    #pragma unroll
    for (int w = 0; w < 8; w++) s += reds[w];

    const float inv = 1.0f / s;
    v0.x *= inv; v0.y *= inv; v0.z *= inv; v0.w *= inv;
    v1.x *= inv; v1.y *= inv; v1.z *= inv; v1.w *= inv;
    row4[tid]       = v0;
    row4[tid + 256] = v1;
}

// ---------------------------------------------------------------------------
// Kernel 4: PV. ctx[q][h*64+d] = sum_k probs[h][q][k] * v[k][h*64+d].
// Per head: M=2048, N=64, K=2048. BM=128, BK=32. 128 threads = 4 warps,
// warp tile 32x64 (acc 2x4): 8 mma per 6 fragment loads.
// grid = (16 qstrips, 16 heads).
// ---------------------------------------------------------------------------
__global__ __launch_bounds__(128) void pv_kernel(
    const float* __restrict__ probs, float* __restrict__ ctx)
{
    constexpr int BM = 128, BK = 32;
    const int h = blockIdx.y;
    const float* P  = probs + (size_t)h * S_LEN * S_LEN;
    const float* vp = g_v + h * HD;

    __shared__ float Ps[BM][BK + 4];
    __shared__ float Vs[BK][HD + 4];

    const int tid  = threadIdx.x;
    const int warp = tid >> 5;       // 0..3, 32-row strip each
    const int row0 = blockIdx.x * BM;

    wmma::fragment<wmma::accumulator, 16, 16, 8, float> acc[2][4];
    #pragma unroll
    for (int i = 0; i < 2; i++)
        #pragma unroll
        for (int j = 0; j < 4; j++)
            wmma::fill_fragment(acc[i][j], 0.0f);

    float4 pR[8], vR[4];
    auto gload = [&](int k0) {
        #pragma unroll
        for (int it = 0; it < 8; it++) {               // P: 128 rows x 8 f4
            int idx = tid + it * 128;
            int r = idx >> 3, c4 = idx & 7;
            pR[it] = *(const float4*)&P[(size_t)(row0 + r) * S_LEN + k0 + c4 * 4];
        }
        #pragma unroll
        for (int it = 0; it < 4; it++) {               // V: 32 krows x 16 f4
            int idx = tid + it * 128;
            int r = idx >> 4, c4 = idx & 15;
            vR[it] = *(const float4*)&vp[(size_t)(k0 + r) * DM + c4 * 4];
        }
    };
    auto sts = [&]() {
        #pragma unroll
        for (int it = 0; it < 8; it++) {
            int idx = tid + it * 128;
            int r = idx >> 3, c4 = idx & 7;
            *(float4*)&Ps[r][c4 * 4] = pR[it];
        }
        #pragma unroll
        for (int it = 0; it < 4; it++) {
            int idx = tid + it * 128;
            int r = idx >> 4, c4 = idx & 15;
            *(float4*)&Vs[r][c4 * 4] = vR[it];
        }
    };

    const int nIter = S_LEN / BK;   // 64
    gload(0);
    sts();
    __syncthreads();

    for (int i = 0; i < nIter; i++) {
        if (i + 1 < nIter) gload((i + 1) * BK);

        #pragma unroll
        for (int kk = 0; kk < BK; kk += 8) {
            wmma::fragment<wmma::matrix_a, 16, 16, 8, wmma::precision::tf32,
                           wmma::row_major> a[2];
            wmma::fragment<wmma::matrix_b, 16, 16, 8, wmma::precision::tf32,
                           wmma::row_major> b[4];
            #pragma unroll
            for (int ii = 0; ii < 2; ii++) {
                wmma::load_matrix_sync(a[ii], &Ps[warp * 32 + ii * 16][kk], BK + 4);
                #pragma unroll
                for (int e = 0; e < a[ii].num_elements; e++)
                    a[ii].x[e] = wmma::__float_to_tf32(a[ii].x[e]);
            }
            #pragma unroll
            for (int j = 0; j < 4; j++) {
                wmma::load_matrix_sync(b[j], &Vs[kk][j * 16], HD + 4);
                #pragma unroll
                for (int e = 0; e < b[j].num_elements; e++)
                    b[j].x[e] = wmma::__float_to_tf32(b[j].x[e]);
            }
            #pragma unroll
            for (int ii = 0; ii < 2; ii++)
                #pragma unroll
                for (int j = 0; j < 4; j++)
                    wmma::mma_sync(acc[ii][j], a[ii], b[j], acc[ii][j]);
        }
        __syncthreads();
        if (i + 1 < nIter) sts();
        __syncthreads();
    }

    #pragma unroll
    for (int i = 0; i < 2; i++)
        #pragma unroll
        for (int j = 0; j < 4; j++)
            wmma::store_matrix_sync(
                &ctx[(size_t)(row0 + warp * 32 + i * 16) * DM + h * HD + j * 16],
                acc[i][j], DM, wmma::mem_row_major);
}

// ---------------------------------------------------------------------------
// Launch. d_out layout: context (2048*1024 floats) then probs (16*2048*2048).
// ---------------------------------------------------------------------------
extern "C" void kernel_launch(void* const* d_in, const int* in_sizes, int n_in,
                              void* d_out, int out_size)
{
    const float* hs = (const float*)d_in[0];
    const float* Wq = (const float*)d_in[1];
    const float* Wk = (const float*)d_in[2];
    const float* Wv = (const float*)d_in[3];

    float* ctx   = (float*)d_out;
    float* probs = ctx + (size_t)S_LEN * DM;

    qkv_gemm_kernel<<<dim3(DM / 64, S_LEN / 128, 3), 256>>>(hs, Wq, Wk, Wv);
    scores_kernel<<<dim3(S_LEN / 128, S_LEN / 128, NH), 256>>>(probs);
    softmax_kernel<<<dim3(NH * S_LEN), 256>>>(probs);
    pv_kernel<<<dim3(S_LEN / 128, NH), 128>>>(probs, ctx);
}

// round 5
// speedup vs baseline: 2.2458x; 2.0960x over previous
#include <cuda_runtime.h>
#include <cuda_fp16.h>
#include <mma.h>
#include <math.h>
#include <cstdint>

using namespace nvcuda;

#define S_LEN 2048
#define DM    1024
#define NH    16
#define HD    64

// Scratch (allocation-guard rules: __device__ globals).
__device__ float  g_q[S_LEN * DM];
__device__ float  g_k[S_LEN * DM];
__device__ float  g_v[S_LEN * DM];
__device__ __half g_xh[S_LEN * DM];
__device__ __half g_wh[3][DM * DM];
__device__ __half g_qh[S_LEN * DM];
__device__ __half g_kh[S_LEN * DM];
__device__ __half g_vh[S_LEN * DM];
__device__ __half g_ph[(size_t)NH * S_LEN * S_LEN];   // half probs copy for PV

// ---------------------------------------------------------------------------
// fp32 -> fp16 converters (float4 -> 4x half per thread).
// ---------------------------------------------------------------------------
__device__ __forceinline__ void cvt4(const float* __restrict__ src,
                                     __half* __restrict__ dst, size_t i)
{
    float4 v = ((const float4*)src)[i];
    __half2 a = __floats2half2_rn(v.x, v.y);
    __half2 b = __floats2half2_rn(v.z, v.w);
    uint2 u;
    u.x = *(const uint32_t*)&a;
    u.y = *(const uint32_t*)&b;
    ((uint2*)dst)[i] = u;
}

__global__ __launch_bounds__(256) void cvt_x_kernel(const float* __restrict__ X)
{
    cvt4(X, g_xh, (size_t)blockIdx.x * 256 + threadIdx.x);
}

__global__ __launch_bounds__(256) void cvt_w_kernel(
    const float* __restrict__ Wq, const float* __restrict__ Wk,
    const float* __restrict__ Wv)
{
    const float* src = (blockIdx.z == 0) ? Wq : (blockIdx.z == 1) ? Wk : Wv;
    cvt4(src, g_wh[blockIdx.z], (size_t)blockIdx.x * 256 + threadIdx.x);
}

__global__ __launch_bounds__(256) void cvt_qkv_kernel()
{
    const float* src = (blockIdx.z == 0) ? g_q : (blockIdx.z == 1) ? g_k : g_v;
    __half*      dst = (blockIdx.z == 0) ? g_qh : (blockIdx.z == 1) ? g_kh : g_vh;
    cvt4(src, dst, (size_t)blockIdx.x * 256 + threadIdx.x);
}

// ---------------------------------------------------------------------------
// Kernel 1: QKV projection, fp16 operands / fp32 accum.
// Y = Xh @ Wh (M=2048, N=1024, K=1024), z selects W.
// BM=128, BN=64, BK=32. 256 threads = 8 warps (4x2), warp tile 32x32.
// ---------------------------------------------------------------------------
__global__ __launch_bounds__(256) void qkv_gemm_kernel()
{
    constexpr int BM = 128, BN = 64, BK = 32;
    const __half* W = g_wh[blockIdx.z];
    float*        Y = (blockIdx.z == 0) ? g_q : (blockIdx.z == 1) ? g_k : g_v;

    __shared__ __align__(16) __half As[BM][BK + 8];
    __shared__ __align__(16) __half Bs[BK][BN + 8];

    const int tid  = threadIdx.x;
    const int warp = tid >> 5;
    const int wm   = warp & 3;
    const int wn   = warp >> 2;

    const int row0 = blockIdx.y * BM;
    const int col0 = blockIdx.x * BN;

    wmma::fragment<wmma::accumulator, 16, 16, 16, float> acc[2][2];
    #pragma unroll
    for (int i = 0; i < 2; i++)
        #pragma unroll
        for (int j = 0; j < 2; j++)
            wmma::fill_fragment(acc[i][j], 0.0f);

    for (int k0 = 0; k0 < DM; k0 += BK) {
        // A tile: 128 rows x 4 int4 (8 halfs each) = 512 loads, 2/thread
        #pragma unroll
        for (int it = 0; it < 2; it++) {
            int idx = tid + it * 256;
            int r = idx >> 2, c = idx & 3;
            *(int4*)&As[r][c * 8] =
                *(const int4*)&g_xh[(size_t)(row0 + r) * DM + k0 + c * 8];
        }
        // B tile: 32 rows x 8 int4 = 256 loads, 1/thread
        {
            int r = tid >> 3, c = tid & 7;
            *(int4*)&Bs[r][c * 8] =
                *(const int4*)&W[(size_t)(k0 + r) * DM + col0 + c * 8];
        }
        __syncthreads();

        #pragma unroll
        for (int kk = 0; kk < BK; kk += 16) {
            wmma::fragment<wmma::matrix_a, 16, 16, 16, __half, wmma::row_major> a[2];
            wmma::fragment<wmma::matrix_b, 16, 16, 16, __half, wmma::row_major> b[2];
            #pragma unroll
            for (int i = 0; i < 2; i++)
                wmma::load_matrix_sync(a[i], &As[wm * 32 + i * 16][kk], BK + 8);
            #pragma unroll
            for (int j = 0; j < 2; j++)
                wmma::load_matrix_sync(b[j], &Bs[kk][wn * 32 + j * 16], BN + 8);
            #pragma unroll
            for (int i = 0; i < 2; i++)
                #pragma unroll
                for (int j = 0; j < 2; j++)
                    wmma::mma_sync(acc[i][j], a[i], b[j], acc[i][j]);
        }
        __syncthreads();
    }

    #pragma unroll
    for (int i = 0; i < 2; i++)
        #pragma unroll
        for (int j = 0; j < 2; j++)
            wmma::store_matrix_sync(
                &Y[(size_t)(row0 + wm * 32 + i * 16) * DM + col0 + wn * 32 + j * 16],
                acc[i][j], DM, wmma::mem_row_major);
}

// ---------------------------------------------------------------------------
// Kernel 2: scores[h][q][k] = (q_h . k_h) / 8, fp16 operands.
// 128x128 tile per block, full d=64 in smem. 8 warps (4x2), warp tile 32x64.
// ---------------------------------------------------------------------------
__global__ __launch_bounds__(256) void scores_kernel(float* __restrict__ probs)
{
    const int h = blockIdx.z;
    __shared__ __align__(16) __half Qs[128][HD + 8];
    __shared__ __align__(16) __half Ks[128][HD + 8];

    const int tid  = threadIdx.x;
    const int warp = tid >> 5;
    const int wm   = warp & 3;   // 4 strips of 32 q-rows
    const int wn   = warp >> 2;  // 2 strips of 64 k-cols

    const int qrow0 = blockIdx.y * 128;
    const int krow0 = blockIdx.x * 128;
    const __half* qp = g_qh + h * HD;
    const __half* kp = g_kh + h * HD;

    // 128 rows x 8 int4 per matrix = 1024 loads each, 4/thread
    #pragma unroll
    for (int it = 0; it < 4; it++) {
        int idx = tid + it * 256;
        int r = idx >> 3, c = idx & 7;
        *(int4*)&Qs[r][c * 8] =
            *(const int4*)&qp[(size_t)(qrow0 + r) * DM + c * 8];
        *(int4*)&Ks[r][c * 8] =
            *(const int4*)&kp[(size_t)(krow0 + r) * DM + c * 8];
    }
    __syncthreads();

    wmma::fragment<wmma::accumulator, 16, 16, 16, float> acc[2][4];
    #pragma unroll
    for (int i = 0; i < 2; i++)
        #pragma unroll
        for (int j = 0; j < 4; j++)
            wmma::fill_fragment(acc[i][j], 0.0f);

    #pragma unroll
    for (int kk = 0; kk < HD; kk += 16) {
        wmma::fragment<wmma::matrix_a, 16, 16, 16, __half, wmma::row_major> a[2];
        wmma::fragment<wmma::matrix_b, 16, 16, 16, __half, wmma::col_major> b[4];
        #pragma unroll
        for (int i = 0; i < 2; i++)
            wmma::load_matrix_sync(a[i], &Qs[wm * 32 + i * 16][kk], HD + 8);
        #pragma unroll
        for (int j = 0; j < 4; j++)
            wmma::load_matrix_sync(b[j], &Ks[wn * 64 + j * 16][kk], HD + 8);
        #pragma unroll
        for (int i = 0; i < 2; i++)
            #pragma unroll
            for (int j = 0; j < 4; j++)
                wmma::mma_sync(acc[i][j], a[i], b[j], acc[i][j]);
    }

    float* outp = probs + (size_t)h * S_LEN * S_LEN;
    #pragma unroll
    for (int i = 0; i < 2; i++)
        #pragma unroll
        for (int j = 0; j < 4; j++) {
            #pragma unroll
            for (int e = 0; e < acc[i][j].num_elements; e++)
                acc[i][j].x[e] *= 0.125f;   // 1/sqrt(64)
            wmma::store_matrix_sync(
                &outp[(size_t)(qrow0 + wm * 32 + i * 16) * S_LEN +
                      krow0 + wn * 64 + j * 16],
                acc[i][j], S_LEN, wmma::mem_row_major);
        }
}

// ---------------------------------------------------------------------------
// Kernel 3: row softmax in place (fp32) + write half copy to g_ph.
// ---------------------------------------------------------------------------
__global__ __launch_bounds__(256) void softmax_kernel(float* __restrict__ probs)
{
    const size_t rowbase = (size_t)blockIdx.x * S_LEN;
    float4* row4 = (float4*)(probs + rowbase);
    __half2* hrow = (__half2*)(g_ph + rowbase);
    const int tid  = threadIdx.x;
    const int lane = tid & 31;
    const int warp = tid >> 5;
    __shared__ float redm[8];
    __shared__ float reds[8];

    float4 v0 = row4[tid];
    float4 v1 = row4[tid + 256];

    float m = fmaxf(fmaxf(fmaxf(v0.x, v0.y), fmaxf(v0.z, v0.w)),
                    fmaxf(fmaxf(v1.x, v1.y), fmaxf(v1.z, v1.w)));
    #pragma unroll
    for (int o = 16; o > 0; o >>= 1)
        m = fmaxf(m, __shfl_xor_sync(0xFFFFFFFFu, m, o));
    if (lane == 0) redm[warp] = m;
    __syncthreads();
    m = redm[0];
    #pragma unroll
    for (int w = 1; w < 8; w++) m = fmaxf(m, redm[w]);

    v0.x = __expf(v0.x - m); v0.y = __expf(v0.y - m);
    v0.z = __expf(v0.z - m); v0.w = __expf(v0.w - m);
    v1.x = __expf(v1.x - m); v1.y = __expf(v1.y - m);
    v1.z = __expf(v1.z - m); v1.w = __expf(v1.w - m);

    float s = (v0.x + v0.y) + (v0.z + v0.w) + (v1.x + v1.y) + (v1.z + v1.w);
    #pragma unroll
    for (int o = 16; o > 0; o >>= 1)
        s += __shfl_xor_sync(0xFFFFFFFFu, s, o);
    if (lane == 0) reds[warp] = s;
    __syncthreads();
    s = 0.0f;
    #pragma unroll
    for (int w = 0; w < 8; w++) s += reds[w];

    const float inv = 1.0f / s;
    v0.x *= inv; v0.y *= inv; v0.z *= inv; v0.w *= inv;
    v1.x *= inv; v1.y *= inv; v1.z *= inv; v1.w *= inv;
    row4[tid]       = v0;
    row4[tid + 256] = v1;

    hrow[2 * tid]             = __floats2half2_rn(v0.x, v0.y);
    hrow[2 * tid + 1]         = __floats2half2_rn(v0.z, v0.w);
    hrow[2 * (tid + 256)]     = __floats2half2_rn(v1.x, v1.y);
    hrow[2 * (tid + 256) + 1] = __floats2half2_rn(v1.z, v1.w);
}

// ---------------------------------------------------------------------------
// Kernel 4: PV, fp16 operands. ctx[q][h*64+d] = sum_k P[h][q][k] * Vh[k][h*64+d].
// BM=128, BN=64(=HD), BK=64. 8 warps (4x2), warp tile 32x32.
// grid = (16 qstrips, 16 heads).
// ---------------------------------------------------------------------------
__global__ __launch_bounds__(256) void pv_kernel(float* __restrict__ ctx)
{
    constexpr int BM = 128, BK = 64;
    const int h = blockIdx.y;
    const __half* P  = g_ph + (size_t)h * S_LEN * S_LEN;
    const __half* vp = g_vh + h * HD;

    __shared__ __align__(16) __half Ps[BM][BK + 8];
    __shared__ __align__(16) __half Vs[BK][HD + 8];

    const int tid  = threadIdx.x;
    const int warp = tid >> 5;
    const int wm   = warp & 3;
    const int wn   = warp >> 2;
    const int row0 = blockIdx.x * BM;

    wmma::fragment<wmma::accumulator, 16, 16, 16, float> acc[2][2];
    #pragma unroll
    for (int i = 0; i < 2; i++)
        #pragma unroll
        for (int j = 0; j < 2; j++)
            wmma::fill_fragment(acc[i][j], 0.0f);

    for (int k0 = 0; k0 < S_LEN; k0 += BK) {
        // P tile: 128 rows x 8 int4 = 1024, 4/thread
        #pragma unroll
        for (int it = 0; it < 4; it++) {
            int idx = tid + it * 256;
            int r = idx >> 3, c = idx & 7;
            *(int4*)&Ps[r][c * 8] =
                *(const int4*)&P[(size_t)(row0 + r) * S_LEN + k0 + c * 8];
        }
        // V tile: 64 rows x 8 int4 = 512, 2/thread
        #pragma unroll
        for (int it = 0; it < 2; it++) {
            int idx = tid + it * 256;
            int r = idx >> 3, c = idx & 7;
            *(int4*)&Vs[r][c * 8] =
                *(const int4*)&vp[(size_t)(k0 + r) * DM + c * 8];
        }
        __syncthreads();

        #pragma unroll
        for (int kk = 0; kk < BK; kk += 16) {
            wmma::fragment<wmma::matrix_a, 16, 16, 16, __half, wmma::row_major> a[2];
            wmma::fragment<wmma::matrix_b, 16, 16, 16, __half, wmma::row_major> b[2];
            #pragma unroll
            for (int i = 0; i < 2; i++)
                wmma::load_matrix_sync(a[i], &Ps[wm * 32 + i * 16][kk], BK + 8);
            #pragma unroll
            for (int j = 0; j < 2; j++)
                wmma::load_matrix_sync(b[j], &Vs[kk][wn * 32 + j * 16], HD + 8);
            #pragma unroll
            for (int i = 0; i < 2; i++)
                #pragma unroll
                for (int j = 0; j < 2; j++)
                    wmma::mma_sync(acc[i][j], a[i], b[j], acc[i][j]);
        }
        __syncthreads();
    }

    #pragma unroll
    for (int i = 0; i < 2; i++)
        #pragma unroll
        for (int j = 0; j < 2; j++)
            wmma::store_matrix_sync(
                &ctx[(size_t)(row0 + wm * 32 + i * 16) * DM + h * HD +
                     wn * 32 + j * 16],
                acc[i][j], DM, wmma::mem_row_major);
}

// ---------------------------------------------------------------------------
// Launch. d_out layout: context (2048*1024 floats) then probs (16*2048*2048).
// ---------------------------------------------------------------------------
extern "C" void kernel_launch(void* const* d_in, const int* in_sizes, int n_in,
                              void* d_out, int out_size)
{
    const float* hs = (const float*)d_in[0];
    const float* Wq = (const float*)d_in[1];
    const float* Wk = (const float*)d_in[2];
    const float* Wv = (const float*)d_in[3];

    float* ctx   = (float*)d_out;
    float* probs = ctx + (size_t)S_LEN * DM;

    cvt_x_kernel<<<dim3(S_LEN * DM / 4 / 256), 256>>>(hs);
    cvt_w_kernel<<<dim3(DM * DM / 4 / 256, 1, 3), 256>>>(Wq, Wk, Wv);
    qkv_gemm_kernel<<<dim3(DM / 64, S_LEN / 128, 3), 256>>>();
    cvt_qkv_kernel<<<dim3(S_LEN * DM / 4 / 256, 1, 3), 256>>>();
    scores_kernel<<<dim3(S_LEN / 128, S_LEN / 128, NH), 256>>>(probs);
    softmax_kernel<<<dim3(NH * S_LEN), 256>>>(probs);
    pv_kernel<<<dim3(S_LEN / 128, NH), 256>>>(ctx);
}